// round 2
// baseline (speedup 1.0000x reference)
#include <cuda_runtime.h>

typedef unsigned long long ULL;

// ---------------- problem sizes ----------------
#define BQ   16384
#define TQ   96
#define FQ   16
#define HQ   64
#define HORQ 24
#define OUTQ 16

// ---------------- weight scratch layout (floats) ----------------
#define OFF_EIH0 0          // 16*256
#define OFF_EHH0 4096       // 64*256
#define OFF_EIH1 20480
#define OFF_EHH1 36864
#define OFF_DIH0 53248
#define OFF_DHH0 69632
#define OFF_DIH1 86016
#define OFF_DHH1 102400
#define OFF_W1T  118784     // 64*64
#define OFF_W2T  122880     // 64*16
#define OFF_BE0  123904     // 256 each
#define OFF_BE1  124160
#define OFF_BD0  124416
#define OFF_BD1  124672
#define OFF_B1   124928     // 64
#define OFF_B2   124992     // 16
#define WBUF_TOTAL 125008

__device__ float g_wbuf[WBUF_TOTAL];

// ---------------- shared memory layout (floats) ----------------
// h arrays are [64][132] (pad 132 keeps float4 alignment, decent banking)
#define XS_OFF   0
#define H0_OFF   (16*132)
#define H1_OFF   (H0_OFF + 64*132)
#define Y1_OFF   (H1_OFF + 64*132)
#define CS_OFF   (Y1_OFF + 64*132)          // c: [2][512][17]
#define SMEM_FLOATS (CS_OFF + 2*512*17)
#define SMEM_BYTES  (SMEM_FLOATS * 4)

// ---------------- f32x2 helpers ----------------
__device__ __forceinline__ ULL pack2(float lo, float hi) {
    ULL r;
    asm("mov.b64 %0, {%1, %2};" : "=l"(r) : "f"(lo), "f"(hi));
    return r;
}
__device__ __forceinline__ float2 unpack2(ULL v) {
    float2 r;
    asm("mov.b64 {%0, %1}, %2;" : "=f"(r.x), "=f"(r.y) : "l"(v));
    return r;
}
__device__ __forceinline__ ULL splat2(float x) { return pack2(x, x); }
__device__ __forceinline__ void ffma2(ULL& d, ULL a, ULL b) {
    asm("fma.rn.f32x2 %0, %1, %2, %0;" : "+l"(d) : "l"(a), "l"(b));
}

// fast activations (MUFU-based, rel err ~1e-6)
__device__ __forceinline__ float sigm_(float x) {
    return __fdividef(1.f, 1.f + __expf(-x));
}
__device__ __forceinline__ float tanh_(float x) {
    return __fdividef(2.f, 1.f + __expf(-2.f * x)) - 1.f;
}

// ---------------- prep kernels (weight transpose + gate permute) ----------------
// LSTM weight W[4H=256][K] row-major; output Wt[k][p], p = u*4+tt for unit u,
// gate type tt (0=i,1=f,2=g,3=o), so orig row = tt*64+u.
__global__ void prep_lstm_mat(const float* __restrict__ src, int dst_off, int K)
{
    int idx = blockIdx.x * blockDim.x + threadIdx.x;
    if (idx >= K * 256) return;
    int k = idx >> 8, p = idx & 255;
    int u = p >> 2, tt = p & 3;
    g_wbuf[dst_off + idx] = src[(tt * 64 + u) * K + k];
}

__global__ void prep_bias(const float* __restrict__ src, int dst_off)
{
    int p = threadIdx.x;            // 256 threads
    int u = p >> 2, tt = p & 3;
    g_wbuf[dst_off + p] = src[tt * 64 + u];
}

__global__ void prep_reg(const float* __restrict__ W1, const float* __restrict__ b1,
                         const float* __restrict__ W2, const float* __restrict__ b2)
{
    int i = blockIdx.x * blockDim.x + threadIdx.x;   // 4096 threads
    if (i < 4096) { int r = i >> 6, k = i & 63; g_wbuf[OFF_W1T + k * 64 + r] = W1[i]; }
    if (i < 1024) { int o = i >> 6, k = i & 63; g_wbuf[OFF_W2T + k * 16 + o] = W2[i]; }
    if (i < 64)  g_wbuf[OFF_B1 + i] = b1[i];
    if (i < 16)  g_wbuf[OFF_B2 + i] = b2[i];
}

// ---------------- main fused kernel ----------------
// 512 threads: gg = tid&31 -> gates g0=gg*8 (units u0=gg*2, u0+1),
//              eg = tid>>5 -> elems e0=eg*8.
// acc[gp*8+e]: gp = gate-pair 0..3 (permuted gates g0+2gp, g0+2gp+1), e = 0..7.

__device__ __forceinline__ void init_acc(ULL* acc, const float* __restrict__ bseg, int g0)
{
#pragma unroll
    for (int gp = 0; gp < 4; gp++) {
        float2 bv = *(const float2*)(bseg + g0 + gp * 2);
        ULL bp = pack2(bv.x, bv.y);
#pragma unroll
        for (int e = 0; e < 8; e++) acc[gp * 8 + e] = bp;
    }
}

template <int K>
__device__ __forceinline__ void gemm_acc(ULL* acc, const float* __restrict__ Wt,
                                         const float* __restrict__ src, int g0, int e0)
{
    const float* wptr = Wt + g0;        // row stride 256
    const float* hptr = src + e0;       // row stride 132
    ulonglong2 w0 = *(const ulonglong2*)(wptr);
    ulonglong2 w1 = *(const ulonglong2*)(wptr + 4);
    float4 ha = *(const float4*)(hptr);
    float4 hb = *(const float4*)(hptr + 4);
#pragma unroll 2
    for (int k = 0; k < K; k++) {
        ULL w[4];
        w[0] = w0.x; w[1] = w0.y; w[2] = w1.x; w[3] = w1.y;
        float4 hc = ha, hd = hb;
        if (k + 1 < K) {                // prefetch next k
            wptr += 256; hptr += 132;
            w0 = *(const ulonglong2*)(wptr);
            w1 = *(const ulonglong2*)(wptr + 4);
            ha = *(const float4*)(hptr);
            hb = *(const float4*)(hptr + 4);
        }
        ULL hp[8];
        hp[0] = splat2(hc.x); hp[1] = splat2(hc.y); hp[2] = splat2(hc.z); hp[3] = splat2(hc.w);
        hp[4] = splat2(hd.x); hp[5] = splat2(hd.y); hp[6] = splat2(hd.z); hp[7] = splat2(hd.w);
#pragma unroll
        for (int gp = 0; gp < 4; gp++)
#pragma unroll
            for (int e = 0; e < 8; e++)
                ffma2(acc[gp * 8 + e], w[gp], hp[e]);
    }
}

// gate activation + state update; writes new h into h_s, updates c in SMEM cbuf
__device__ __forceinline__ void lstm_act(const ULL* acc, float* cbuf,
                                         float* __restrict__ h_s, int u0, int e0)
{
#pragma unroll
    for (int ui = 0; ui < 2; ui++) {
        float hv[8];
#pragma unroll
        for (int e = 0; e < 8; e++) {
            float2 if_ = unpack2(acc[(ui * 2 + 0) * 8 + e]);   // (i, f)
            float2 go_ = unpack2(acc[(ui * 2 + 1) * 8 + e]);   // (g, o)
            float cold = cbuf[ui * 8 + e];
            float cn = sigm_(if_.y) * cold + sigm_(if_.x) * tanh_(go_.x);
            cbuf[ui * 8 + e] = cn;
            hv[e] = sigm_(go_.y) * tanh_(cn);
        }
        float4* dst = (float4*)(h_s + (u0 + ui) * 132 + e0);
        dst[0] = make_float4(hv[0], hv[1], hv[2], hv[3]);
        dst[1] = make_float4(hv[4], hv[5], hv[6], hv[7]);
    }
}

__global__ void __launch_bounds__(512, 1)
seq2seq_main(const float* __restrict__ X, const float* __restrict__ biasB,
             float* __restrict__ out)
{
    extern __shared__ float sm[];
    float* x_s  = sm + XS_OFF;
    float* h0_s = sm + H0_OFF;
    float* h1_s = sm + H1_OFF;
    float* y1_s = sm + Y1_OFF;
    float* c_s  = sm + CS_OFF;

    const int tid = threadIdx.x;
    const int gg  = tid & 31;
    const int eg  = tid >> 5;
    const int g0  = gg * 8;
    const int e0  = eg * 8;
    const int u0  = gg * 2;
    const int b0  = blockIdx.x * 128;

    float* c0buf = c_s + tid * 17;
    float* c1buf = c_s + 512 * 17 + tid * 17;

    // zero all state
    for (int i = tid; i < SMEM_FLOATS; i += 512) sm[i] = 0.f;
    __syncthreads();

    ULL acc[32];

    // ================= encoder =================
    for (int t = 0; t < TQ; t++) {
        // stage x_t tile: x_s[f][e]
        {
            int e = tid >> 2, f = (tid & 3) * 4;
            float4 v = *(const float4*)(X + (size_t)(b0 + e) * (TQ * FQ) + t * FQ + f);
            x_s[(f + 0) * 132 + e] = v.x;
            x_s[(f + 1) * 132 + e] = v.y;
            x_s[(f + 2) * 132 + e] = v.z;
            x_s[(f + 3) * 132 + e] = v.w;
        }
        __syncthreads();
        // layer 0: z = b + x@Wih0^T + h0@Whh0^T
        init_acc(acc, g_wbuf + OFF_BE0, g0);
        gemm_acc<16>(acc, g_wbuf + OFF_EIH0, x_s, g0, e0);
        gemm_acc<64>(acc, g_wbuf + OFF_EHH0, h0_s, g0, e0);
        __syncthreads();
        lstm_act(acc, c0buf, h0_s, u0, e0);
        __syncthreads();
        // layer 1: z = b + h0@Wih1^T + h1@Whh1^T
        init_acc(acc, g_wbuf + OFF_BE1, g0);
        gemm_acc<64>(acc, g_wbuf + OFF_EIH1, h0_s, g0, e0);
        gemm_acc<64>(acc, g_wbuf + OFF_EHH1, h1_s, g0, e0);
        __syncthreads();
        lstm_act(acc, c1buf, h1_s, u0, e0);
        __syncthreads();
    }

    // ================= decoder =================
    // carry: dh0 = enc h0 (h0_s), dh1 = enc h1 (h1_s)  -- already in place; c = 0
#pragma unroll
    for (int j = 0; j < 16; j++) { c0buf[j] = 0.f; c1buf[j] = 0.f; }

    // head gemm2 mapping + per-batch bias preload
    const int o2  = tid & 15;
    const int e0b = (tid >> 4) * 4;
    float bb[4];
#pragma unroll
    for (int j = 0; j < 4; j++)
        bb[j] = biasB[(size_t)(b0 + e0b + j) * OUTQ + o2];
    const float b2v = g_wbuf[OFF_B2 + o2];

    for (int s = 0; s < HORQ; s++) {
        // dec layer 0: input = dh1 (h1_s), hidden = dh0 (h0_s)
        init_acc(acc, g_wbuf + OFF_BD0, g0);
        gemm_acc<64>(acc, g_wbuf + OFF_DIH0, h1_s, g0, e0);
        gemm_acc<64>(acc, g_wbuf + OFF_DHH0, h0_s, g0, e0);
        __syncthreads();
        lstm_act(acc, c0buf, h0_s, u0, e0);     // h0_s := new dh0
        __syncthreads();
        // dec layer 1: input = new dh0, hidden = dh1
        init_acc(acc, g_wbuf + OFF_BD1, g0);
        gemm_acc<64>(acc, g_wbuf + OFF_DIH1, h0_s, g0, e0);
        gemm_acc<64>(acc, g_wbuf + OFF_DHH1, h1_s, g0, e0);
        __syncthreads();
        lstm_act(acc, c1buf, h1_s, u0, e0);     // h1_s := new dh1
        __syncthreads();

        // head gemm1: y1 = relu(dh1 @ W1^T + b1), rows u0,u0+1 per thread
        {
            ULL a2[8];
            float2 bv = *(const float2*)(g_wbuf + OFF_B1 + u0);
            ULL bp = pack2(bv.x, bv.y);
#pragma unroll
            for (int e = 0; e < 8; e++) a2[e] = bp;
            const float* wp = g_wbuf + OFF_W1T + u0;   // row stride 64
            const float* hp = h1_s + e0;
#pragma unroll 4
            for (int k = 0; k < 64; k++) {
                ULL w = *(const ULL*)(wp); wp += 64;
                float4 hA = *(const float4*)(hp);
                float4 hB = *(const float4*)(hp + 4);
                hp += 132;
                ffma2(a2[0], w, splat2(hA.x));
                ffma2(a2[1], w, splat2(hA.y));
                ffma2(a2[2], w, splat2(hA.z));
                ffma2(a2[3], w, splat2(hA.w));
                ffma2(a2[4], w, splat2(hB.x));
                ffma2(a2[5], w, splat2(hB.y));
                ffma2(a2[6], w, splat2(hB.z));
                ffma2(a2[7], w, splat2(hB.w));
            }
#pragma unroll
            for (int e = 0; e < 8; e++) {
                float2 v = unpack2(a2[e]);
                y1_s[(u0 + 0) * 132 + e0 + e] = fmaxf(v.x, 0.f);
                y1_s[(u0 + 1) * 132 + e0 + e] = fmaxf(v.y, 0.f);
            }
        }
        __syncthreads();

        // head gemm2: y = y1 @ W2^T + b2 + last_bias; out[b][s][o]
        {
            float a3[4] = { b2v, b2v, b2v, b2v };
            const float* wp2 = g_wbuf + OFF_W2T + o2;  // row stride 16
            const float* yp  = y1_s + e0b;
#pragma unroll 4
            for (int k = 0; k < 64; k++) {
                float w = wp2[k * 16];
                float4 yv = *(const float4*)(yp + k * 132);
                a3[0] = fmaf(w, yv.x, a3[0]);
                a3[1] = fmaf(w, yv.y, a3[1]);
                a3[2] = fmaf(w, yv.z, a3[2]);
                a3[3] = fmaf(w, yv.w, a3[3]);
            }
#pragma unroll
            for (int j = 0; j < 4; j++)
                out[(size_t)(b0 + e0b + j) * (HORQ * OUTQ) + s * OUTQ + o2] = a3[j] + bb[j];
        }
        __syncthreads();
    }
}

// ---------------- launch ----------------
extern "C" void kernel_launch(void* const* d_in, const int* in_sizes, int n_in,
                              void* d_out, int out_size)
{
    (void)in_sizes; (void)n_in; (void)out_size;
    const float* X    = (const float*)d_in[0];
    const float* bias = (const float*)d_in[1];
    // d_in[2] = X_mask (all ones, unused by reference)
    const float* eih0 = (const float*)d_in[3];
    const float* ehh0 = (const float*)d_in[4];
    const float* eb0  = (const float*)d_in[5];
    const float* eih1 = (const float*)d_in[6];
    const float* ehh1 = (const float*)d_in[7];
    const float* eb1  = (const float*)d_in[8];
    const float* dih0 = (const float*)d_in[9];
    const float* dhh0 = (const float*)d_in[10];
    const float* db0  = (const float*)d_in[11];
    const float* dih1 = (const float*)d_in[12];
    const float* dhh1 = (const float*)d_in[13];
    const float* db1  = (const float*)d_in[14];
    const float* rW1  = (const float*)d_in[15];
    const float* rb1  = (const float*)d_in[16];
    const float* rW2  = (const float*)d_in[17];
    const float* rb2  = (const float*)d_in[18];
    float* out = (float*)d_out;

    prep_lstm_mat<<<16, 256>>>(eih0, OFF_EIH0, 16);
    prep_lstm_mat<<<64, 256>>>(ehh0, OFF_EHH0, 64);
    prep_lstm_mat<<<64, 256>>>(eih1, OFF_EIH1, 64);
    prep_lstm_mat<<<64, 256>>>(ehh1, OFF_EHH1, 64);
    prep_lstm_mat<<<64, 256>>>(dih0, OFF_DIH0, 64);
    prep_lstm_mat<<<64, 256>>>(dhh0, OFF_DHH0, 64);
    prep_lstm_mat<<<64, 256>>>(dih1, OFF_DIH1, 64);
    prep_lstm_mat<<<64, 256>>>(dhh1, OFF_DHH1, 64);
    prep_bias<<<1, 256>>>(eb0, OFF_BE0);
    prep_bias<<<1, 256>>>(eb1, OFF_BE1);
    prep_bias<<<1, 256>>>(db0, OFF_BD0);
    prep_bias<<<1, 256>>>(db1, OFF_BD1);
    prep_reg<<<16, 256>>>(rW1, rb1, rW2, rb2);

    cudaFuncSetAttribute(seq2seq_main,
                         cudaFuncAttributeMaxDynamicSharedMemorySize, SMEM_BYTES);
    seq2seq_main<<<128, 512, SMEM_BYTES>>>(X, bias, out);
}